// round 3
// baseline (speedup 1.0000x reference)
#include <cuda_runtime.h>
#include <math.h>

#define B_ 8
#define N_ 2048
#define W_ 64
#define R_ 4
#define EPS_ 1e-8f
#define TI_ 128

typedef unsigned long long u64;

// ---------------- device scratch (no cudaMalloc allowed) ----------------
__device__ float g_fwd [B_*R_*N_];
__device__ float g_bwdp[B_*16*R_*N_];   // per-tile bwd partials (4 MB)
__device__ float g_cw  [B_*R_*N_];
__device__ float g_rw  [B_*R_*N_];
__device__ float g_kn  [B_*R_];
__device__ float g_beta[B_*R_];
__device__ float g_gate[B_*R_*3];
__device__ float g_P   [B_*R_];
__device__ float g_S   [B_*R_];

// ---------------- f32x2 packed helpers (sm_103a) ----------------
__device__ __forceinline__ u64 pk(float a, float b){
    u64 r; asm("mov.b64 %0,{%1,%2};" : "=l"(r) : "f"(a), "f"(b)); return r;
}
__device__ __forceinline__ void upk(u64 x, float& a, float& b){
    asm("mov.b64 {%0,%1},%2;" : "=f"(a), "=f"(b) : "l"(x));
}
__device__ __forceinline__ u64 add2(u64 a, u64 b){
    u64 d; asm("add.rn.f32x2 %0,%1,%2;" : "=l"(d) : "l"(a), "l"(b)); return d;
}
__device__ __forceinline__ u64 sub2(u64 a, u64 b){
    u64 d; asm("sub.rn.f32x2 %0,%1,%2;" : "=l"(d) : "l"(a), "l"(b)); return d;
}
__device__ __forceinline__ u64 mul2(u64 a, u64 b){
    u64 d; asm("mul.rn.f32x2 %0,%1,%2;" : "=l"(d) : "l"(a), "l"(b)); return d;
}
__device__ __forceinline__ u64 fma2(u64 a, u64 b, u64 c){
    u64 d; asm("fma.rn.f32x2 %0,%1,%2,%3;" : "=l"(d) : "l"(a), "l"(b), "l"(c)); return d;
}

// ================= setup: P_r, S_r, key norms, betas, gates =================
__global__ void k_setup(const float* __restrict__ controls, const float* __restrict__ ww,
                        const float* __restrict__ p, const float* __restrict__ prw)
{
    int br = blockIdx.x, b = br >> 2, r = br & 3;
    int tid = threadIdx.x, warp = tid >> 5, lane = tid & 31;

    const float* prwr = prw + br*N_;
    const float* pb   = p   + b*N_;
    const float* wb   = ww  + b*N_;
    float accP = 0.f, accS = 0.f;
    for (int k = tid; k < N_; k += 256) {
        float t = prwr[k];
        accP += pb[k]*t;
        accS += wb[k]*t;
    }
    float kq = 0.f;
    if (tid < W_) { float kv = controls[b*272 + r*64 + tid]; kq = kv*kv; }

    #pragma unroll
    for (int off = 16; off; off >>= 1) {
        accP += __shfl_xor_sync(~0u, accP, off);
        accS += __shfl_xor_sync(~0u, accS, off);
        kq   += __shfl_xor_sync(~0u, kq,   off);
    }
    __shared__ float sm[3][8];
    if (lane == 0) { sm[0][warp]=accP; sm[1][warp]=accS; sm[2][warp]=kq; }
    __syncthreads();
    if (tid == 0) {
        float P=0.f, S=0.f, K=0.f;
        #pragma unroll
        for (int w2 = 0; w2 < 8; w2++) { P += sm[0][w2]; S += sm[1][w2]; K += sm[2][w2]; }
        g_P[br] = P; g_S[br] = S; g_kn[br] = sqrtf(K);
        float x  = controls[b*272 + 256 + r];
        g_beta[br] = 1.f + ((x > 15.f) ? x : log1pf(__expf(x)));
        float e0 = controls[b*272 + 260 + r*3 + 0];
        float e1 = controls[b*272 + 260 + r*3 + 1];
        float e2 = controls[b*272 + 260 + r*3 + 2];
        float m  = fmaxf(e0, fmaxf(e1, e2));
        float x0 = __expf(e0-m), x1 = __expf(e1-m), x2 = __expf(e2-m);
        float inv = 1.f/(x0+x1+x2);
        g_gate[br*3+0] = x0*inv; g_gate[br*3+1] = x1*inv; g_gate[br*3+2] = x2*inv;
    }
}

// ================= content scores: one warp per (b,n) =================
__global__ void k_content(const float* __restrict__ mem, const float* __restrict__ controls)
{
    int warp = threadIdx.x >> 5, lane = threadIdx.x & 31;
    int gw = blockIdx.x * 8 + warp;          // 0..16383
    int b = gw >> 11, n = gw & 2047;

    const float* mrow = mem + ((size_t)(b*N_ + n))*W_;
    float m0 = mrow[lane], m1 = mrow[lane+32];
    const float* kb = controls + b*272;

    float mn = m0*m0 + m1*m1;
    float d0 = m0*kb[0*64+lane] + m1*kb[0*64+32+lane];
    float d1 = m0*kb[1*64+lane] + m1*kb[1*64+32+lane];
    float d2 = m0*kb[2*64+lane] + m1*kb[2*64+32+lane];
    float d3 = m0*kb[3*64+lane] + m1*kb[3*64+32+lane];

    #pragma unroll
    for (int off = 16; off; off >>= 1) {
        mn += __shfl_xor_sync(~0u, mn, off);
        d0 += __shfl_xor_sync(~0u, d0, off);
        d1 += __shfl_xor_sync(~0u, d1, off);
        d2 += __shfl_xor_sync(~0u, d2, off);
        d3 += __shfl_xor_sync(~0u, d3, off);
    }
    if (lane == 0) {
        float mns = sqrtf(mn);
        int base = b*4;
        g_cw[(base+0)*N_ + n] = g_beta[base+0] * d0 / (g_kn[base+0]*mns + EPS_);
        g_cw[(base+1)*N_ + n] = g_beta[base+1] * d1 / (g_kn[base+1]*mns + EPS_);
        g_cw[(base+2)*N_ + n] = g_beta[base+2] * d2 / (g_kn[base+2]*mns + EPS_);
        g_cw[(base+3)*N_ + n] = g_beta[base+3] * d3 / (g_kn[base+3]*mns + EPS_);
    }
}

// ================= softmax over n (in place in g_cw), one block per (b,r) =================
__global__ void k_softmax()
{
    int br = blockIdx.x;
    int tid = threadIdx.x, warp = tid >> 5, lane = tid & 31;
    float v[8];
    float mx = -INFINITY;
    #pragma unroll
    for (int k = 0; k < 8; k++) { v[k] = g_cw[br*N_ + tid + k*256]; mx = fmaxf(mx, v[k]); }

    __shared__ float sred[8];
    __shared__ float sbc;
    #pragma unroll
    for (int off = 16; off; off >>= 1) mx = fmaxf(mx, __shfl_xor_sync(~0u, mx, off));
    if (lane == 0) sred[warp] = mx;
    __syncthreads();
    if (tid == 0) { float m = sred[0]; for (int i=1;i<8;i++) m = fmaxf(m, sred[i]); sbc = m; }
    __syncthreads();
    mx = sbc;

    float s = 0.f;
    #pragma unroll
    for (int k = 0; k < 8; k++) { v[k] = __expf(v[k]-mx); s += v[k]; }
    #pragma unroll
    for (int off = 16; off; off >>= 1) s += __shfl_xor_sync(~0u, s, off);
    __syncthreads();                    // everyone done reading sbc(max)
    if (lane == 0) sred[warp] = s;
    __syncthreads();
    if (tid == 0) { float t = 0.f; for (int i=0;i<8;i++) t += sred[i]; sbc = 1.f/t; }
    __syncthreads();
    float inv = sbc;
    #pragma unroll
    for (int k = 0; k < 8; k++) g_cw[br*N_ + tid + k*256] = v[k]*inv;
}

// ================= HOT: one pass over prev_links =================
// 128 blocks = 8 b x 16 tiles of 128 rows. 512 threads. Warp w owns j-range
// [w*128, w*128+128); each lane owns 8 j; lanes 0-15 process even row of the
// pair, lanes 16-31 odd row. fwd reduced 4-stage butterfly per 16-lane half,
// staged in smem; bwd accumulated in registers, flushed to g_bwdp.
__global__ void __launch_bounds__(512, 1)
k_stream(const float* __restrict__ L, const float* __restrict__ ww,
         const float* __restrict__ prw)
{
    int b  = blockIdx.x >> 4;
    int tile = blockIdx.x & 15;
    int i0 = tile * TI_;
    int tid = threadIdx.x, w = tid >> 5, lane = tid & 31;
    int half = lane >> 4, h = lane & 15;

    __shared__ float s_a[TI_];
    __shared__ float s_pi[R_][TI_];
    __shared__ u64   s_part[2][TI_][16];

    if (tid < TI_) s_a[tid] = 1.f - ww[b*N_ + i0 + tid];
    if (tid < R_*TI_) { int r = tid >> 7, i = tid & 127; s_pi[r][i] = prw[(b*4+r)*N_ + i0 + i]; }
    __syncthreads();

    int j0 = w*128 + h*8;
    u64 pj[4][4];
    #pragma unroll
    for (int r = 0; r < 4; r++) {
        float4 A  = *(const float4*)(prw + (b*4+r)*N_ + j0);
        float4 Bv = *(const float4*)(prw + (b*4+r)*N_ + j0 + 4);
        pj[r][0] = pk(A.x, A.y);  pj[r][1] = pk(A.z, A.w);
        pj[r][2] = pk(Bv.x, Bv.y); pj[r][3] = pk(Bv.z, Bv.w);
    }
    float4 wA = *(const float4*)(ww + b*N_ + j0);
    float4 wB = *(const float4*)(ww + b*N_ + j0 + 4);
    u64 wj[4] = { pk(wA.x,wA.y), pk(wA.z,wA.w), pk(wB.x,wB.y), pk(wB.z,wB.w) };

    u64 bw[4][4];
    #pragma unroll
    for (int r = 0; r < 4; r++)
        #pragma unroll
        for (int k = 0; k < 4; k++) bw[r][k] = pk(0.f, 0.f);

    const float* Lbase = L + ((size_t)(b*N_ + i0))*N_ + j0;
    float4 cA = __ldcs((const float4*)(Lbase + (size_t)half*N_));
    float4 cB = __ldcs((const float4*)(Lbase + (size_t)half*N_ + 4));

    for (int g = 0; g < TI_/2; ++g) {
        int row = 2*g + half;
        float4 nA = cA, nB = cB;
        if (g + 1 < TI_/2) {
            const float* nx = Lbase + (size_t)(row + 2)*N_;
            nA = __ldcs((const float4*)nx);
            nB = __ldcs((const float4*)(nx + 4));
        }
        u64 l[4] = { pk(cA.x,cA.y), pk(cA.z,cA.w), pk(cB.x,cB.y), pk(cB.z,cB.w) };
        float a = s_a[row];
        u64 av = pk(a, a);
        u64 c[4];
        #pragma unroll
        for (int k = 0; k < 4; k++) c[k] = mul2(sub2(av, wj[k]), l[k]);

        float f[4];
        #pragma unroll
        for (int r = 0; r < 4; r++) {
            u64 t = mul2(c[0], pj[r][0]);
            t = fma2(c[1], pj[r][1], t);
            t = fma2(c[2], pj[r][2], t);
            t = fma2(c[3], pj[r][3], t);
            float x, y; upk(t, x, y); f[r] = x + y;
            float pi = s_pi[r][row];
            u64 pr = pk(pi, pi);
            bw[r][0] = fma2(c[0], pr, bw[r][0]);
            bw[r][1] = fma2(c[1], pr, bw[r][1]);
            bw[r][2] = fma2(c[2], pr, bw[r][2]);
            bw[r][3] = fma2(c[3], pr, bw[r][3]);
        }
        u64 f01 = pk(f[0], f[1]), f23 = pk(f[2], f[3]);
        #pragma unroll
        for (int m = 8; m; m >>= 1) {
            f01 = add2(f01, __shfl_xor_sync(~0u, f01, m));
            f23 = add2(f23, __shfl_xor_sync(~0u, f23, m));
        }
        if (h == 0) { s_part[0][row][w] = f01; s_part[1][row][w] = f23; }
        cA = nA; cB = nB;
    }

    // combine bwd across the two halves, then flush this block's partial
    #pragma unroll
    for (int r = 0; r < 4; r++)
        #pragma unroll
        for (int k = 0; k < 4; k++)
            bw[r][k] = add2(bw[r][k], __shfl_xor_sync(~0u, bw[r][k], 16));
    if (half == 0) {
        #pragma unroll
        for (int r = 0; r < 4; r++) {
            float* dst = g_bwdp + ((size_t)(b*16 + tile)*4 + r)*N_ + j0;
            ulonglong2 v0; v0.x = bw[r][0]; v0.y = bw[r][1];
            ulonglong2 v1; v1.x = bw[r][2]; v1.y = bw[r][3];
            *(ulonglong2*)dst       = v0;
            *(ulonglong2*)(dst + 4) = v1;
        }
    }
    __syncthreads();

    // phase 2: fold 16 warp partials -> g_fwd. One (row,r) per thread.
    {
        int row = tid >> 2, r = tid & 3;
        const float* sp = (const float*)&s_part[r >> 1][row][0];
        float s = 0.f;
        #pragma unroll
        for (int w2 = 0; w2 < 16; w2++) s += sp[w2*2 + (r & 1)];
        g_fwd[(b*4 + r)*N_ + i0 + row] = s;
    }
}

// ================= epilogue: rank-1 + diag fixes, gate mix -> g_rw =================
__global__ void k_epi(const float* __restrict__ L, const float* __restrict__ ww,
                      const float* __restrict__ p, const float* __restrict__ prw)
{
    int br = blockIdx.x, b = br >> 2, r = br & 3;
    float g0 = g_gate[br*3], g1 = g_gate[br*3+1], g2 = g_gate[br*3+2];
    float P = g_P[br], S = g_S[br];
    for (int n = threadIdx.x; n < N_; n += 256) {
        float bp = 0.f;
        #pragma unroll
        for (int t = 0; t < 16; t++)
            bp += g_bwdp[((size_t)(b*16 + t)*4 + r)*N_ + n];
        float wn  = ww[b*N_ + n];
        float pn  = p [b*N_ + n];
        float prn = prw[br*N_ + n];
        float Lnn = L[((size_t)(b*N_ + n))*N_ + n];
        float ell = (1.f - 2.f*wn)*Lnn + wn*pn;
        float fwd = g_fwd[br*N_ + n] + wn*P - ell*prn;
        float bwd = bp + pn*S - ell*prn;
        g_rw[br*N_ + n] = g0*fwd + g1*bwd + g2*g_cw[br*N_ + n];
    }
}

// ================= read vector: out[b,r,w] = sum_n mem[b,n,w] * rw[b,r,n] =================
__global__ void __launch_bounds__(512)
k_readvec(const float* __restrict__ mem, float* __restrict__ out)
{
    int b = blockIdx.x;
    int tid = threadIdx.x, w = tid >> 5, lane = tid & 31;
    __shared__ float s_rw[R_][N_];
    __shared__ float s_acc[16][R_][W_];
    for (int k = tid; k < R_*N_; k += 512) s_rw[k >> 11][k & 2047] = g_rw[b*R_*N_ + k];
    __syncthreads();

    float2 acc[4];
    #pragma unroll
    for (int r = 0; r < 4; r++) { acc[r].x = 0.f; acc[r].y = 0.f; }
    for (int n = w*128; n < w*128 + 128; ++n) {
        float2 m = *(const float2*)(mem + ((size_t)(b*N_ + n))*W_ + lane*2);
        #pragma unroll
        for (int r = 0; r < 4; r++) {
            float rv = s_rw[r][n];
            acc[r].x += m.x*rv;
            acc[r].y += m.y*rv;
        }
    }
    #pragma unroll
    for (int r = 0; r < 4; r++) {
        s_acc[w][r][lane*2]   = acc[r].x;
        s_acc[w][r][lane*2+1] = acc[r].y;
    }
    __syncthreads();
    if (tid < 256) {
        int r = tid >> 6, wd = tid & 63;
        float s = 0.f;
        #pragma unroll
        for (int k = 0; k < 16; k++) s += s_acc[k][r][wd];
        out[b*R_*W_ + r*W_ + wd] = s;
    }
}

// ================= launcher =================
extern "C" void kernel_launch(void* const* d_in, const int* in_sizes, int n_in,
                              void* d_out, int out_size)
{
    const float* mem      = (const float*)d_in[0];
    const float* controls = (const float*)d_in[1];
    const float* ww       = (const float*)d_in[2];
    const float* L        = (const float*)d_in[3];
    const float* p        = (const float*)d_in[4];
    const float* prw      = (const float*)d_in[5];
    float* out = (float*)d_out;

    k_setup  <<<B_*R_, 256>>>(controls, ww, p, prw);
    k_content<<<B_*N_/8, 256>>>(mem, controls);
    k_softmax<<<B_*R_, 256>>>();
    k_stream <<<B_*16, 512>>>(L, ww, prw);
    k_epi    <<<B_*R_, 256>>>(L, ww, p, prw);
    k_readvec<<<B_, 512>>>(mem, out);
}